// round 17
// baseline (speedup 1.0000x reference)
#include <cuda_runtime.h>
#include <cuda_fp16.h>
#include <cstdint>

// Problem constants (fixed by the reference)
constexpr int D    = 256;
constexpr int D4   = 64;       // float4 per row
constexpr int NP   = 100000;   // n_pois
constexpr int NH   = 50000;    // n_hyperedges
constexpr int NNZC = 1600000;  // nnz

constexpr int SCAN_TILE = 2048;    // elements per scan tile (1024 thr x 2)
constexpr int NT_T = (NH + SCAN_TILE - 1) / SCAN_TILE;   // 25
constexpr int NT_S = (NP + SCAN_TILE - 1) / SCAN_TILE;   // 49

// ---------------------------------------------------------------------------
// Scratch: __device__ globals (no cudaMalloc allowed)
// ---------------------------------------------------------------------------
__device__ int   g_offs_t[NH + 1];
__device__ int   g_cur_t [NH + 1];
__device__ int   g_offs_s[NP + 1];
__device__ int   g_cur_s [NP + 1];
__device__ int   g_tsum_t[64];
__device__ int   g_tsum_s[64];

__device__ int   g_cols_t[NNZC];
__device__ float g_vals_t[NNZC];
__device__ int   g_cols_s[NNZC];
__device__ float g_vals_s[NNZC];

__device__ __half g_pois_h   [(size_t)NP * D];  // 51.2 MB fp16 gather copy of pois
__device__ __half g_msg_tar_h[(size_t)NH * D];  // 25.6 MB fp16 tar-spmm output
__device__ __half g_embs1_h  [(size_t)NP * D];  // 51.2 MB fp16 embs1 (gather + epilogue)
__device__ float  g_w[3];

// ---------------------------------------------------------------------------
// softmax over the 3 layer-attention logits -> g_w
// ---------------------------------------------------------------------------
__global__ void softmax3_kernel(const float* __restrict__ att) {
    if (threadIdx.x == 0) {
        float a0 = att[0], a1 = att[1], a2 = att[2];
        float m  = fmaxf(a0, fmaxf(a1, a2));
        float e0 = expf(a0 - m), e1 = expf(a1 - m), e2 = expf(a2 - m);
        float s  = e0 + e1 + e2;
        g_w[0] = e0 / s; g_w[1] = e1 / s; g_w[2] = e2 / s;
    }
}

// ---------------------------------------------------------------------------
// fp32 -> fp16 convert (float4 in, 4 halves out per thread)
// ---------------------------------------------------------------------------
__global__ void f2h_kernel(const float4* __restrict__ in, uint2* __restrict__ out,
                           int n4) {
    for (int i = blockIdx.x * blockDim.x + threadIdx.x; i < n4;
         i += gridDim.x * blockDim.x) {
        float4 v = in[i];
        __half2 h0 = __float22half2_rn(make_float2(v.x, v.y));
        __half2 h1 = __float22half2_rn(make_float2(v.z, v.w));
        uint2 r;
        r.x = *reinterpret_cast<uint32_t*>(&h0);
        r.y = *reinterpret_cast<uint32_t*>(&h1);
        out[i] = r;
    }
}

// ---------------------------------------------------------------------------
// CSR build (fused for both matrices):
//   zero2 -> hist2 -> tilesum_both -> scantsum_both -> scanfinal_both -> place2
// ---------------------------------------------------------------------------
__global__ void zero2_kernel(int* __restrict__ a, int na,
                             int* __restrict__ b, int nb) {
    int tid = blockIdx.x * blockDim.x + threadIdx.x;
    int stride = gridDim.x * blockDim.x;
    for (int i = tid; i < na; i += stride) a[i] = 0;
    for (int i = tid; i < nb; i += stride) b[i] = 0;
}

__global__ void hist2_kernel(const int* __restrict__ rows_t,
                             const int* __restrict__ rows_s,
                             int* __restrict__ cnt_t, int* __restrict__ cnt_s,
                             int nnz) {
    for (int i = blockIdx.x * blockDim.x + threadIdx.x; i < nnz;
         i += gridDim.x * blockDim.x) {
        atomicAdd(&cnt_t[rows_t[i]], 1);
        atomicAdd(&cnt_s[rows_s[i]], 1);
    }
}

// per-tile sums for BOTH count arrays; blocks [0,NT_T) -> tar, rest -> src
__global__ void tilesum_both_kernel(const int* __restrict__ cnt_t,
                                    const int* __restrict__ cnt_s,
                                    int* __restrict__ tsum_t,
                                    int* __restrict__ tsum_s) {
    __shared__ int wsum[32];
    const bool is_t = blockIdx.x < NT_T;
    const int tile  = is_t ? blockIdx.x : blockIdx.x - NT_T;
    const int n     = is_t ? NH : NP;
    const int* cnt  = is_t ? cnt_t : cnt_s;
    int* tsum       = is_t ? tsum_t : tsum_s;

    int base = tile * SCAN_TILE;
    int v = 0;
    for (int i = threadIdx.x; i < SCAN_TILE; i += blockDim.x) {
        int idx = base + i;
        if (idx < n) v += cnt[idx];
    }
    int lane = threadIdx.x & 31, wid = threadIdx.x >> 5;
    for (int d = 16; d; d >>= 1) v += __shfl_down_sync(~0u, v, d);
    if (lane == 0) wsum[wid] = v;
    __syncthreads();
    if (wid == 0) {
        int w = wsum[lane];
        for (int d = 16; d; d >>= 1) w += __shfl_down_sync(~0u, w, d);
        if (lane == 0) tsum[tile] = w;
    }
}

// exclusive scan of both tiny tile-sum arrays (warp 0 -> tar, warp 1 -> src)
__global__ void scantsum_both_kernel(int* __restrict__ tsum_t,
                                     int* __restrict__ tsum_s) {
    if (threadIdx.x == 0) {
        int run = 0;
        for (int i = 0; i < NT_T; i++) { int v = tsum_t[i]; tsum_t[i] = run; run += v; }
        tsum_t[NT_T] = run;
    } else if (threadIdx.x == 32) {
        int run = 0;
        for (int i = 0; i < NT_S; i++) { int v = tsum_s[i]; tsum_s[i] = run; run += v; }
        tsum_s[NT_S] = run;
    }
}

// per-tile exclusive scan + tile offset -> offs (and cursor copy); both arrays
__global__ void scanfinal_both_kernel(const int* __restrict__ cnt_t,
                                      const int* __restrict__ cnt_s,
                                      const int* __restrict__ toff_t,
                                      const int* __restrict__ toff_s,
                                      int* __restrict__ offs_t, int* __restrict__ cur_t,
                                      int* __restrict__ offs_s, int* __restrict__ cur_s) {
    __shared__ int wsum[32];
    const bool is_t = blockIdx.x < NT_T;
    const int tile  = is_t ? blockIdx.x : blockIdx.x - NT_T;
    const int n     = is_t ? NH : NP;
    const int nt    = is_t ? NT_T : NT_S;
    const int* cnt  = is_t ? cnt_t : cnt_s;
    const int* toff = is_t ? toff_t : toff_s;
    int* offs       = is_t ? offs_t : offs_s;
    int* cur        = is_t ? cur_t : cur_s;

    int base = tile * SCAN_TILE;
    int t = threadIdx.x;
    int i0 = base + 2 * t, i1 = i0 + 1;
    int a = (i0 < n) ? cnt[i0] : 0;
    int b = (i1 < n) ? cnt[i1] : 0;
    int s = a + b;
    int lane = t & 31, wid = t >> 5;
    int x = s;                                 // inclusive warp scan
    for (int d = 1; d < 32; d <<= 1) {
        int y = __shfl_up_sync(~0u, x, d);
        if (lane >= d) x += y;
    }
    if (lane == 31) wsum[wid] = x;
    __syncthreads();
    if (wid == 0) {
        int w = wsum[lane];
        int xx = w;
        for (int d = 1; d < 32; d <<= 1) {
            int y = __shfl_up_sync(~0u, xx, d);
            if (lane >= d) xx += y;
        }
        wsum[lane] = xx - w;                   // exclusive warp offsets
    }
    __syncthreads();
    int excl = (x - s) + wsum[wid] + toff[tile];
    if (i0 < n) { offs[i0] = excl;     cur[i0] = excl; }
    if (i1 < n) { offs[i1] = excl + a; cur[i1] = excl + a; }
    if (tile == 0 && t == 0) offs[n] = toff[nt];
}

// fused placement for both matrices
__global__ void place2_kernel(const int* __restrict__ rows_t,
                              const int* __restrict__ cols_t_in,
                              const float* __restrict__ vals_t_in,
                              const int* __restrict__ rows_s,
                              const int* __restrict__ cols_s_in,
                              const float* __restrict__ vals_s_in,
                              int* __restrict__ cur_t, int* __restrict__ cur_s,
                              int* __restrict__ cols_t, float* __restrict__ vals_t,
                              int* __restrict__ cols_s, float* __restrict__ vals_s,
                              int nnz) {
    for (int i = blockIdx.x * blockDim.x + threadIdx.x; i < nnz;
         i += gridDim.x * blockDim.x) {
        int rt = rows_t[i];
        int pt = atomicAdd(&cur_t[rt], 1);
        cols_t[pt] = cols_t_in[i];
        vals_t[pt] = vals_t_in[i];
        int rs = rows_s[i];
        int ps = atomicAdd(&cur_s[rs], 1);
        cols_s[ps] = cols_s_in[i];
        vals_s[ps] = vals_s_in[i];
    }
}

// ---------------------------------------------------------------------------
// Gather-only CSR SpMM over fp16 dense rows, fp32 accumulate, warp-per-row.
//   MODE 0: msg_tar_h[r] = (half)acc                        (tar spmm)
//   MODE 1: embs1_h[r] = (half)((relu(acc)*d1 + pois)*d2)   (layer-1 src spmm)
//   MODE 2: out[r] = w0*pois + w1*e1h + w2*((relu(acc)*d1 + e1h)*d2)
// ---------------------------------------------------------------------------
__device__ __forceinline__ void acc_half4(float4& a, uint32_t lo, uint32_t hi,
                                          float vk) {
    __half2 h0 = *reinterpret_cast<__half2*>(&lo);
    __half2 h1 = *reinterpret_cast<__half2*>(&hi);
    float2 f0 = __half22float2(h0);
    float2 f1 = __half22float2(h1);
    a.x += f0.x * vk; a.y += f0.y * vk;
    a.z += f1.x * vk; a.w += f1.y * vk;
}

__device__ __forceinline__ float4 h4_to_f4(uint2 h) {
    float2 f0 = __half22float2(*reinterpret_cast<__half2*>(&h.x));
    float2 f1 = __half22float2(*reinterpret_cast<__half2*>(&h.y));
    return make_float4(f0.x, f0.y, f1.x, f1.y);
}

__device__ __forceinline__ uint2 f4_to_h4(float4 f) {
    __half2 h0 = __float22half2_rn(make_float2(f.x, f.y));
    __half2 h1 = __float22half2_rn(make_float2(f.z, f.w));
    uint2 r;
    r.x = *reinterpret_cast<uint32_t*>(&h0);
    r.y = *reinterpret_cast<uint32_t*>(&h1);
    return r;
}

template <int MODE>
__global__ void __launch_bounds__(256)
spmm_csr_kernel(float4* __restrict__ out, uint2* __restrict__ outh,
                const __half* __restrict__ dense,
                const int* __restrict__ offs, const int* __restrict__ cols,
                const float* __restrict__ vals, int nrows,
                const float4* __restrict__ pois, const uint2* __restrict__ e1h,
                const float4* __restrict__ d1, const float4* __restrict__ d2) {
    const int lane = threadIdx.x & 31;
    int warp = (blockIdx.x * blockDim.x + threadIdx.x) >> 5;
    const int nw = (gridDim.x * blockDim.x) >> 5;

    for (int r = warp; r < nrows; r += nw) {
        const int start = offs[r];
        const int end   = offs[r + 1];

        float4 a0 = make_float4(0.f, 0.f, 0.f, 0.f);
        float4 a1 = make_float4(0.f, 0.f, 0.f, 0.f);

        int j0 = start;
        for (; j0 + 32 <= end; j0 += 32) {          // full-warp chunks
            const int   c = cols[j0 + lane];
            const float v = vals[j0 + lane];
            #pragma unroll 4
            for (int k = 0; k < 32; k++) {
                const int   ck = __shfl_sync(0xffffffffu, c, k);
                const float vk = __shfl_sync(0xffffffffu, v, k);
                const uint2* __restrict__ s =
                    reinterpret_cast<const uint2*>(dense + (size_t)ck * D) + lane;
                uint2 x0 = __ldg(s);
                uint2 x1 = __ldg(s + 32);
                acc_half4(a0, x0.x, x0.y, vk);
                acc_half4(a1, x1.x, x1.y, vk);
            }
        }
        if (j0 < end) {                              // tail chunk
            int j = j0 + lane;
            int   c = 0;
            float v = 0.f;
            if (j < end) { c = cols[j]; v = vals[j]; }
            const int cnt = end - j0;
            for (int k = 0; k < cnt; k++) {
                const int   ck = __shfl_sync(0xffffffffu, c, k);
                const float vk = __shfl_sync(0xffffffffu, v, k);
                const uint2* __restrict__ s =
                    reinterpret_cast<const uint2*>(dense + (size_t)ck * D) + lane;
                uint2 x0 = __ldg(s);
                uint2 x1 = __ldg(s + 32);
                acc_half4(a0, x0.x, x0.y, vk);
                acc_half4(a1, x1.x, x1.y, vk);
            }
        }

        const size_t o0 = (size_t)r * D4 + lane;
        const size_t o1 = o0 + 32;

        if (MODE == 0) {
            outh[o0] = f4_to_h4(a0);
            outh[o1] = f4_to_h4(a1);
        } else if (MODE == 1) {
            float4 p0 = pois[o0], p1 = pois[o1];
            float4 m0 = d1[o0],   m1 = d1[o1];
            float4 n0 = d2[o0],   n1 = d2[o1];
            float4 r0, r1;
            r0.x = (fmaxf(a0.x, 0.f) * m0.x + p0.x) * n0.x;
            r0.y = (fmaxf(a0.y, 0.f) * m0.y + p0.y) * n0.y;
            r0.z = (fmaxf(a0.z, 0.f) * m0.z + p0.z) * n0.z;
            r0.w = (fmaxf(a0.w, 0.f) * m0.w + p0.w) * n0.w;
            r1.x = (fmaxf(a1.x, 0.f) * m1.x + p1.x) * n1.x;
            r1.y = (fmaxf(a1.y, 0.f) * m1.y + p1.y) * n1.y;
            r1.z = (fmaxf(a1.z, 0.f) * m1.z + p1.z) * n1.z;
            r1.w = (fmaxf(a1.w, 0.f) * m1.w + p1.w) * n1.w;
            outh[o0] = f4_to_h4(r0);
            outh[o1] = f4_to_h4(r1);
        } else {
            const float w0 = g_w[0], w1 = g_w[1], w2 = g_w[2];
            float4 p0 = pois[o0], p1 = pois[o1];
            float4 e0 = h4_to_f4(e1h[o0]), e1v = h4_to_f4(e1h[o1]);
            float4 m0 = d1[o0],   m1 = d1[o1];
            float4 n0 = d2[o0],   n1 = d2[o1];
            float4 r0, r1;
            r0.x = w0 * p0.x + w1 * e0.x + w2 * ((fmaxf(a0.x, 0.f) * m0.x + e0.x) * n0.x);
            r0.y = w0 * p0.y + w1 * e0.y + w2 * ((fmaxf(a0.y, 0.f) * m0.y + e0.y) * n0.y);
            r0.z = w0 * p0.z + w1 * e0.z + w2 * ((fmaxf(a0.z, 0.f) * m0.z + e0.z) * n0.z);
            r0.w = w0 * p0.w + w1 * e0.w + w2 * ((fmaxf(a0.w, 0.f) * m0.w + e0.w) * n0.w);
            r1.x = w0 * p1.x + w1 * e1v.x + w2 * ((fmaxf(a1.x, 0.f) * m1.x + e1v.x) * n1.x);
            r1.y = w0 * p1.y + w1 * e1v.y + w2 * ((fmaxf(a1.y, 0.f) * m1.y + e1v.y) * n1.y);
            r1.z = w0 * p1.z + w1 * e1v.z + w2 * ((fmaxf(a1.z, 0.f) * m1.z + e1v.z) * n1.z);
            r1.w = w0 * p1.w + w1 * e1v.w + w2 * ((fmaxf(a1.w, 0.f) * m1.w + e1v.w) * n1.w);
            out[o0] = r0;
            out[o1] = r1;
        }
    }
}

// ---------------------------------------------------------------------------
// kernel_launch — graph-capturable, allocation-free
// ---------------------------------------------------------------------------
extern "C" void kernel_launch(void* const* d_in, const int* in_sizes, int n_in,
                              void* d_out, int out_size) {
    const float* pois     = (const float*)d_in[0];
    const float* tar_vals = (const float*)d_in[1];
    const float* src_vals = (const float*)d_in[2];
    const float* att      = (const float*)d_in[3];
    const float* drop1    = (const float*)d_in[4];   // [2, NP, D]
    const float* drop2    = (const float*)d_in[5];   // [2, NP, D]
    const int*   tar_rows = (const int*)d_in[6];
    const int*   tar_cols = (const int*)d_in[7];
    const int*   src_rows = (const int*)d_in[8];
    const int*   src_cols = (const int*)d_in[9];
    float4* out = (float4*)d_out;

    int *p_offs_t, *p_cur_t, *p_offs_s, *p_cur_s, *p_tsum_t, *p_tsum_s;
    int *p_cols_t, *p_cols_s;
    float *p_vals_t, *p_vals_s;
    __half *p_pois_h, *p_mt_h, *p_e1_h;
    cudaGetSymbolAddress((void**)&p_offs_t, g_offs_t);
    cudaGetSymbolAddress((void**)&p_cur_t,  g_cur_t);
    cudaGetSymbolAddress((void**)&p_offs_s, g_offs_s);
    cudaGetSymbolAddress((void**)&p_cur_s,  g_cur_s);
    cudaGetSymbolAddress((void**)&p_tsum_t, g_tsum_t);
    cudaGetSymbolAddress((void**)&p_tsum_s, g_tsum_s);
    cudaGetSymbolAddress((void**)&p_cols_t, g_cols_t);
    cudaGetSymbolAddress((void**)&p_vals_t, g_vals_t);
    cudaGetSymbolAddress((void**)&p_cols_s, g_cols_s);
    cudaGetSymbolAddress((void**)&p_vals_s, g_vals_s);
    cudaGetSymbolAddress((void**)&p_pois_h, g_pois_h);
    cudaGetSymbolAddress((void**)&p_mt_h,   g_msg_tar_h);
    cudaGetSymbolAddress((void**)&p_e1_h,   g_embs1_h);

    softmax3_kernel<<<1, 32>>>(att);

    // fp16 copy of pois for layer-1 tar gather
    f2h_kernel<<<2048, 256>>>((const float4*)pois, (uint2*)p_pois_h, NP * D / 4);

    // ---- fused CSR build for both matrices ----
    zero2_kernel<<<128, 256>>>(p_cur_t, NH + 1, p_cur_s, NP + 1);
    hist2_kernel<<<1024, 256>>>(tar_rows, src_rows, p_cur_t, p_cur_s, NNZC);
    tilesum_both_kernel<<<NT_T + NT_S, 1024>>>(p_cur_t, p_cur_s, p_tsum_t, p_tsum_s);
    scantsum_both_kernel<<<1, 64>>>(p_tsum_t, p_tsum_s);
    scanfinal_both_kernel<<<NT_T + NT_S, 1024>>>(p_cur_t, p_cur_s, p_tsum_t, p_tsum_s,
                                                 p_offs_t, p_cur_t, p_offs_s, p_cur_s);
    place2_kernel<<<1024, 256>>>(tar_rows, tar_cols, tar_vals,
                                 src_rows, src_cols, src_vals,
                                 p_cur_t, p_cur_s,
                                 p_cols_t, p_vals_t, p_cols_s, p_vals_s, NNZC);

    const int BT = 256;                       // 8 warps / block
    const int GB_T = (NH + 7) / 8;            // warp per hyperedge row
    const int GB_S = (NP + 7) / 8;            // warp per poi row
    const size_t ND = (size_t)NP * D;

    // ---- layer 1 ----
    spmm_csr_kernel<0><<<GB_T, BT>>>(nullptr, (uint2*)p_mt_h, p_pois_h,
                                     p_offs_t, p_cols_t, p_vals_t, NH,
                                     nullptr, nullptr, nullptr, nullptr);
    spmm_csr_kernel<1><<<GB_S, BT>>>(nullptr, (uint2*)p_e1_h, p_mt_h,
                                     p_offs_s, p_cols_s, p_vals_s, NP,
                                     (const float4*)pois, nullptr,
                                     (const float4*)drop1, (const float4*)drop2);

    // ---- layer 2 ----
    spmm_csr_kernel<0><<<GB_T, BT>>>(nullptr, (uint2*)p_mt_h, p_e1_h,
                                     p_offs_t, p_cols_t, p_vals_t, NH,
                                     nullptr, nullptr, nullptr, nullptr);
    spmm_csr_kernel<2><<<GB_S, BT>>>(out, nullptr, p_mt_h,
                                     p_offs_s, p_cols_s, p_vals_s, NP,
                                     (const float4*)pois, (const uint2*)p_e1_h,
                                     (const float4*)(drop1 + ND),
                                     (const float4*)(drop2 + ND));
}